// round 1
// baseline (speedup 1.0000x reference)
#include <cuda_runtime.h>
#include <math.h>

#define BSZ 8
#define CCH 512
#define TT  8192
#define NEL (BSZ*CCH*TT)   // 33554432
#define KW  3
#define WSZ (CCH*CCH*KW)   // 786432

// ---------------- scratch (static device globals; no allocation) -------------
__device__ float g_act[NEL];   // activation output (reused for act1 and act2)
__device__ float g_c1[NEL];    // conv1 output
__device__ float g_w1[WSZ];    // weight-normed conv1 weights
__device__ float g_w2[WSZ];    // weight-normed conv2 weights
__device__ float g_a2c[2*CCH]; // [0..511]=2*exp(alpha1), [512..]=2*exp(alpha2)
__device__ float g_binv[2*CCH];// 1/(2*exp(beta)+eps) for stage 1 and 2

// ---------------- kernel 1: weight norm + snake param precompute -------------
__global__ void wnorm_kernel(const float* __restrict__ v, const float* __restrict__ g,
                             float* __restrict__ w,
                             const float* __restrict__ alpha, const float* __restrict__ beta,
                             float* __restrict__ a2out, float* __restrict__ binvout)
{
    int co = blockIdx.x;
    const float* vc = v + co * (CCH * KW);
    float s = 0.f;
    for (int i = threadIdx.x; i < CCH * KW; i += 256) {
        float t = vc[i];
        s += t * t;
    }
    __shared__ float red[256];
    red[threadIdx.x] = s;
    __syncthreads();
    for (int off = 128; off > 0; off >>= 1) {
        if (threadIdx.x < off) red[threadIdx.x] += red[threadIdx.x + off];
        __syncthreads();
    }
    float scale = g[co] / sqrtf(red[0]);
    for (int i = threadIdx.x; i < CCH * KW; i += 256)
        w[co * (CCH * KW) + i] = vc[i] * scale;
    if (threadIdx.x == 0) {
        a2out[co]   = 2.f * expf(alpha[co]);
        binvout[co] = 1.f / (2.f * expf(beta[co]) + 1e-9f);
    }
}

// ---------------- kernel 2: fused SnakeBeta Activation1d ---------------------
// Activation1d(up2 linear, snakebeta, avgpool2) collapses to:
//   u0 = (t>0) ? 0.25*x[t-1] + 0.75*x[t] : x[t]
//   u1 = 0.75*x[t] + 0.25*((t<T-1) ? x[t+1] : x[t])
//   out = 0.5*(f(u0)+f(u1)),  f(u) = u + (1-cos(2a*u)) / (2b+eps)
__global__ void snake_act_kernel(const float* __restrict__ in,
                                 const float* __restrict__ a2,
                                 const float* __restrict__ binv,
                                 float* __restrict__ out)
{
    int idx = blockIdx.x * blockDim.x + threadIdx.x;
    if (idx >= NEL) return;
    int t = idx & (TT - 1);
    int c = (idx >> 13) & (CCH - 1);

    float x0 = in[idx];
    float xm = (t > 0)      ? in[idx - 1] : 0.f;
    float xp = (t < TT - 1) ? in[idx + 1] : x0;

    float u0 = (t > 0) ? fmaf(0.25f, xm, 0.75f * x0) : x0;
    float u1 = fmaf(0.25f, xp, 0.75f * x0);

    float aa = a2[c];
    float bi = binv[c];
    float y0 = u0 + (1.f - cosf(aa * u0)) * bi;
    float y1 = u1 + (1.f - cosf(aa * u1)) * bi;
    out[idx] = 0.5f * (y0 + y1);
}

// ---------------- kernel 3: K=3 conv as tiled implicit GEMM ------------------
// Block tile: 64 cout x 64 t, one batch; ci processed in chunks of 16 in smem.
// Thread tile: 4 cout (strided by 16) x 4 t (contiguous). 48 FFMA / 18 LDS per ci.
#define BT   64
#define BCO  64
#define CIC  16

__global__ __launch_bounds__(256)
void conv3_kernel(const float* __restrict__ A, const float* __restrict__ W,
                  const float* __restrict__ bias, const float* __restrict__ resid,
                  float* __restrict__ out)
{
    __shared__ float As[CIC][BT + 2];
    __shared__ float Ws[BCO][CIC][KW];

    const int b   = blockIdx.z;
    const int co0 = blockIdx.y * BCO;
    const int t0  = blockIdx.x * BT;
    const int tid = threadIdx.x;
    const int tx  = tid & 15;   // t group:  t = t0 + 4*tx + j
    const int ty  = tid >> 4;   // co group: co = co0 + ty + 16*i

    const float* Ab = A + (b * CCH) * TT;

    float acc[4][4];
#pragma unroll
    for (int i = 0; i < 4; i++)
#pragma unroll
        for (int j = 0; j < 4; j++) acc[i][j] = 0.f;

    for (int ci0 = 0; ci0 < CCH; ci0 += CIC) {
        // stage A tile (with halo, zero-padded)
        for (int i = tid; i < CIC * (BT + 2); i += 256) {
            int r = i / (BT + 2);
            int c = i - r * (BT + 2);
            int t = t0 - 1 + c;
            As[r][c] = (t >= 0 && t < TT) ? Ab[(ci0 + r) * TT + t] : 0.f;
        }
        // stage W tile
        for (int i = tid; i < BCO * CIC * KW; i += 256) {
            int co  = i / (CIC * KW);
            int rem = i - co * (CIC * KW);
            int ci  = rem / KW;
            int k   = rem - ci * KW;
            Ws[co][ci][k] = W[((co0 + co) * CCH + (ci0 + ci)) * KW + k];
        }
        __syncthreads();

#pragma unroll
        for (int ci = 0; ci < CIC; ci++) {
            float a[6];
#pragma unroll
            for (int q = 0; q < 6; q++) a[q] = As[ci][4 * tx + q];
#pragma unroll
            for (int i = 0; i < 4; i++) {
                float w0 = Ws[ty + 16 * i][ci][0];
                float w1 = Ws[ty + 16 * i][ci][1];
                float w2 = Ws[ty + 16 * i][ci][2];
#pragma unroll
                for (int j = 0; j < 4; j++) {
                    acc[i][j] = fmaf(w0, a[j],     acc[i][j]);
                    acc[i][j] = fmaf(w1, a[j + 1], acc[i][j]);
                    acc[i][j] = fmaf(w2, a[j + 2], acc[i][j]);
                }
            }
        }
        __syncthreads();
    }

#pragma unroll
    for (int i = 0; i < 4; i++) {
        int co = co0 + ty + 16 * i;
        float bb = bias[co];
#pragma unroll
        for (int j = 0; j < 4; j++) {
            int t   = t0 + 4 * tx + j;
            int idx = (b * CCH + co) * TT + t;
            float v = acc[i][j] + bb;
            if (resid) v += resid[idx];
            out[idx] = v;
        }
    }
}

// ---------------------------------- launch -----------------------------------
extern "C" void kernel_launch(void* const* d_in, const int* in_sizes, int n_in,
                              void* d_out, int out_size)
{
    const float* x      = (const float*)d_in[0];
    const float* v1     = (const float*)d_in[1];
    const float* g1     = (const float*)d_in[2];
    const float* bias1  = (const float*)d_in[3];
    const float* v2     = (const float*)d_in[4];
    const float* g2     = (const float*)d_in[5];
    const float* bias2  = (const float*)d_in[6];
    const float* alpha1 = (const float*)d_in[7];
    const float* beta1  = (const float*)d_in[8];
    const float* alpha2 = (const float*)d_in[9];
    const float* beta2  = (const float*)d_in[10];
    float* out = (float*)d_out;

    float *w1, *w2, *act, *c1, *a2c, *binv;
    cudaGetSymbolAddress((void**)&w1,   g_w1);
    cudaGetSymbolAddress((void**)&w2,   g_w2);
    cudaGetSymbolAddress((void**)&act,  g_act);
    cudaGetSymbolAddress((void**)&c1,   g_c1);
    cudaGetSymbolAddress((void**)&a2c,  g_a2c);
    cudaGetSymbolAddress((void**)&binv, g_binv);

    // 1) weight norm + snake params
    wnorm_kernel<<<CCH, 256>>>(v1, g1, w1, alpha1, beta1, a2c,       binv);
    wnorm_kernel<<<CCH, 256>>>(v2, g2, w2, alpha2, beta2, a2c + CCH, binv + CCH);

    // 2) act1(x) -> g_act
    snake_act_kernel<<<NEL / 256, 256>>>(x, a2c, binv, act);

    // 3) conv1(g_act) -> g_c1
    dim3 cgrid(TT / BT, CCH / BCO, BSZ);
    conv3_kernel<<<cgrid, 256>>>(act, w1, bias1, nullptr, c1);

    // 4) act2(g_c1) -> g_act (reuse)
    snake_act_kernel<<<NEL / 256, 256>>>(c1, a2c + CCH, binv + CCH, act);

    // 5) conv2(g_act) + residual x -> out
    conv3_kernel<<<cgrid, 256>>>(act, w2, bias2, x, out);
}